// round 14
// baseline (speedup 1.0000x reference)
#include <cuda_runtime.h>
#include <cuda_bf16.h>
#include <cuda_fp16.h>
#include <math.h>
#include <stdint.h>

// Problem dims (fixed by the dataset)
#define BB 4
#define NN 96
#define TT 512
#define KK 12
#define GG 8

typedef unsigned long long u64;

// ---------------- device scratch (no cudaMalloc allowed) ----------------
__device__ float g_splat[(size_t)BB * KK * TT * 128];     // (B,K,T,2,8,8)

// ---------------- small helpers ----------------
__device__ __forceinline__ u64 pack2(float x) {
    u64 r; asm("mov.b64 %0, {%1, %1};" : "=l"(r) : "f"(x)); return r;
}
__device__ __forceinline__ u64 packpair(float a, float b) {
    u64 r; asm("mov.b64 %0, {%1, %2};" : "=l"(r) : "f"(a), "f"(b)); return r;
}
__device__ __forceinline__ void ffma2(u64& d, u64 a, u64 b) {
    asm("fma.rn.f32x2 %0, %1, %2, %0;" : "+l"(d) : "l"(a), "l"(b));
}
__device__ __forceinline__ void unpack2(float& lo, float& hi, u64 v) {
    asm("mov.b64 {%0, %1}, %2;" : "=f"(lo), "=f"(hi) : "l"(v));
}
__device__ __forceinline__ float softplusf(float x) {
    return (x > 20.0f) ? x : log1pf(expf(x));
}
__device__ __forceinline__ float softplus_fast(float x) {
    return (x > 20.0f) ? x : __logf(1.0f + __expf(x));
}
__device__ __forceinline__ float tanh_fast(float x) {
    float xc = fminf(fmaxf(x, -15.0f), 15.0f);
    float t = __expf(2.0f * xc);
    return (t - 1.0f) * __fdividef(1.0f, t + 1.0f);
}
// Pade [5/4] tanh, valid |x|<=1
__device__ __forceinline__ float tanh_pade(float x) {
    float x2 = x * x;
    float p = fmaf(fmaf(x2, 1.0f, 105.0f), x2, 945.0f);
    float q = fmaf(fmaf(15.0f, x2, 420.0f), x2, 945.0f);
    return __fdividef(x * p, q);
}
__device__ __forceinline__ float acos_fast01(float c) {
    float p = sqrtf(fmaxf(1.0f - c, 0.0f));
    float poly = fmaf(c, fmaf(c, fmaf(c, -0.0187293f, 0.0742610f), -0.2121144f), 1.5707288f);
    return p * poly;
}
// GELU via 3-term A&S erf (|eps| <= 2.5e-5)
__device__ __forceinline__ float gelu_fast(float x) {
    float ax = fabsf(x);
    float z = ax * 0.70710678118f;
    float t = __fdividef(1.0f, fmaf(0.47047f, z, 1.0f));
    float poly = t * fmaf(t, fmaf(t, 0.7478556f, -0.0958798f), 0.3480242f);
    float e = __expf(-z * z);
    float erfv = fmaf(-poly, e, 1.0f);
    return fmaf(0.5f * ax, erfv, 0.5f * x);
}
__device__ __forceinline__ uint32_t smem_u32(const void* p) {
    uint32_t a;
    asm("{ .reg .u64 t; cvta.to.shared.u64 t, %1; cvt.u32.u64 %0, t; }" : "=r"(a) : "l"(p));
    return a;
}
#define CVTPACK_F16(r, a, b) \
    asm("cvt.rn.f16x2.f32 %0, %2, %1;" : "=r"(r) : "f"(a), "f"(b))
#define LDMATRIX_X4(r0, r1, r2, r3, addr) \
    asm volatile("ldmatrix.sync.aligned.m8n8.x4.shared.b16 {%0,%1,%2,%3}, [%4];" \
                 : "=r"(r0), "=r"(r1), "=r"(r2), "=r"(r3) : "r"(addr))
#define MMA16816(c, a, b0, b1) \
    asm volatile("mma.sync.aligned.m16n8k16.row.col.f32.f16.f16.f32 " \
                 "{%0,%1,%2,%3},{%4,%5,%6,%7},{%8,%9},{%0,%1,%2,%3};" \
                 : "+f"((c)[0]), "+f"((c)[1]), "+f"((c)[2]), "+f"((c)[3]) \
                 : "r"((a)[0]), "r"((a)[1]), "r"((a)[2]), "r"((a)[3]), \
                   "r"(b0), "r"(b1))

// ---------------- kernel 1: splat rasterization (leads built in-block) -----
#define NC 32

__global__ __launch_bounds__(384) void splat_kernel(
    const float* __restrict__ mu, const float* __restrict__ sigma0,
    const float* __restrict__ sigma_vel, const float* __restrict__ amplitude,
    const float* __restrict__ sh_base, const float* __restrict__ sh_vel,
    const float* __restrict__ p0, const float* __restrict__ p_vel,
    const float* __restrict__ tau_raw, const float* __restrict__ gam_raw,
    const float* __restrict__ ra, const float* __restrict__ la,
    const float* __restrict__ ll, const float* __restrict__ chest) {
    __shared__ float  sLead[KK][18];
    __shared__ float  sPN[NN][16];        // {gauss, ppx, ppy, ppz, invpn, sh_dyn[9]}
    __shared__ float2 sAA[NC][KK];
    __shared__ float2 sKu2[NC][KK][4];    // ku pairs (aligned for LDS.64)
    __shared__ float  sKv[NC][KK][9];

    int t = blockIdx.x, b = blockIdx.y;
    int tid = threadIdx.x;

    // ---- leads: 12 threads build sLead directly (was prep_kernel) ----
    if (tid < KK) {
        int k = tid;
        float vx, vy, vz;
        float rax = ra[0], ray = ra[1], raz = ra[2];
        float lax = la[0], lay = la[1], laz = la[2];
        float llx = ll[0], lly = ll[1], llz = ll[2];
        switch (k) {
            case 0: vx = lax - rax; vy = lay - ray; vz = laz - raz; break;
            case 1: vx = llx - rax; vy = lly - ray; vz = llz - raz; break;
            case 2: vx = llx - lax; vy = lly - lay; vz = llz - laz; break;
            case 3: vx = rax - 0.5f * (lax + llx); vy = ray - 0.5f * (lay + lly); vz = raz - 0.5f * (laz + llz); break;
            case 4: vx = lax - 0.5f * (rax + llx); vy = lay - 0.5f * (ray + lly); vz = laz - 0.5f * (raz + llz); break;
            case 5: vx = llx - 0.5f * (rax + lax); vy = lly - 0.5f * (ray + lay); vz = llz - 0.5f * (raz + laz); break;
            default:
                vx = chest[(k - 6) * 3 + 0]; vy = chest[(k - 6) * 3 + 1]; vz = chest[(k - 6) * 3 + 2];
                break;
        }
        float n = sqrtf(vx * vx + vy * vy + vz * vz);
        float d = fmaxf(n, 1e-6f);
        float Lx = vx / d, Ly = vy / d, Lz = vz / d;
        float e1x = 0.0f, e1y = Lz, e1z = -Ly;
        float n1 = sqrtf(e1y * e1y + e1z * e1z);
        if (n1 < 1e-4f) { e1x = -Lz; e1y = 0.0f; e1z = Lx; n1 = sqrtf(e1x * e1x + e1z * e1z); }
        float d1 = fmaxf(n1, 1e-6f);
        e1x /= d1; e1y /= d1; e1z /= d1;
        float e2x = e1y * Lz - e1z * Ly;
        float e2y = e1z * Lx - e1x * Lz;
        float e2z = e1x * Ly - e1y * Lx;
        float n2 = sqrtf(e2x * e2x + e2y * e2y + e2z * e2z);
        float d2 = fmaxf(n2, 1e-6f);
        e2x /= d2; e2y /= d2; e2z /= d2;
        float* o = sLead[k];
        o[0] = Lx; o[1] = Ly; o[2] = Lz;
        o[3] = e1x; o[4] = e1y; o[5] = e1z;
        o[6] = e2x; o[7] = e2y; o[8] = e2z;
        o[9]  = 0.282095f;
        o[10] = -0.488603f * Ly;
        o[11] = 0.488603f * Lz;
        o[12] = -0.488603f * Lx;
        o[13] = 1.092548f * Lx * Ly;
        o[14] = -1.092548f * Ly * Lz;
        o[15] = 0.315392f * (3.0f * Lz * Lz - 1.0f);
        o[16] = -1.092548f * Lx * Lz;
        o[17] = 0.546274f * (Lx * Lx - Ly * Ly);
    }

    float tau = softplusf(tau_raw[0]) + 0.06f;
    float inv2tau2 = 0.5f / (tau * tau);
    float gamma = softplusf(gam_raw[0]) + 1e-6f;
    float tval = (float)t * (1.0f / (float)(TT - 1));
    const float DLT = 2.0f / 7.0f;
    float aD = inv2tau2 * DLT;
    float Cc = __expf(-2.0f * aD * DLT);   // exp recurrence constant

    // ---- phase 0: per-n quantities, computed ONCE (96 threads) ----
    if (tid < NN) {
        int bn = b * NN + tid;
        float dt = tval - mu[bn];
        float sig = softplus_fast(sigma0[bn] + sigma_vel[bn] * dt) + 1e-3f;
        float z = dt * __fdividef(1.0f, sig);
        float gauss = amplitude[bn] * __expf(-0.5f * z * z);
        float prx = p0[bn * 3 + 0] + p_vel[bn * 3 + 0] * dt;
        float pry = p0[bn * 3 + 1] + p_vel[bn * 3 + 1] * dt;
        float prz = p0[bn * 3 + 2] + p_vel[bn * 3 + 2] * dt;
        float nrm = fmaxf(sqrtf(prx * prx + pry * pry + prz * prz), 1e-8f);
        float th = tanh_fast(nrm);
        float sc = th * __fdividef(1.0f, nrm);
        float* o = sPN[tid];
        o[0] = gauss;
        o[1] = prx * sc;
        o[2] = pry * sc;
        o[3] = prz * sc;
        o[4] = __fdividef(1.0f, fmaxf(th, 1e-8f));
        #pragma unroll
        for (int m = 0; m < 9; ++m)
            o[5 + m] = fmaf(sh_vel[bn * 9 + m], dt, sh_base[bn * 9 + m]);
    }

    int warp = tid >> 5, lane = tid & 31;
    int px0 = lane * 2;
    int hh = px0 >> 3, w0 = px0 & 7;
    int w02 = w0 >> 1;
    u64 accA = 0ull, accS = 0ull;   // packed (acc00,acc01), (acc10,acc11)

    int nl = tid / KK, kk = tid - nl * KK;
    __syncthreads();

    for (int c = 0; c < NN / NC; ++c) {
        // ---- phase 1: per-(n,k) ----
        {
            int n = c * NC + nl;
            const float* pn = sPN[n];
            const float* Ld = sLead[kk];
            float gauss = pn[0], ppx = pn[1], ppy = pn[2], ppz = pn[3], invpn = pn[4];
            float u = tanh_pade(ppx * Ld[3] + ppy * Ld[4] + ppz * Ld[5]);
            float v = tanh_pade(ppx * Ld[6] + ppy * Ld[7] + ppz * Ld[8]);
            float cosl = (ppx * Ld[0] + ppy * Ld[1] + ppz * Ld[2]) * invpn;
            float hem = fmaxf(cosl, 0.0f);
            float ccv = fminf(fmaxf(cosl, -1.0f + 1e-6f), 1.0f - 1e-6f);
            float theta = acos_fast01(ccv);
            float weight = hem * __expf(-gamma * theta * theta);
            float A = gauss * weight;
            float shp = 0.0f;
            #pragma unroll
            for (int m = 0; m < 9; ++m)
                shp = fmaf(pn[5 + m], Ld[9 + m], shp);
            sAA[nl][kk] = make_float2(A, A * shp);
            // Gaussian grid via exp recurrence: 2 exp per axis; ku as pairs
            {
                float d0 = u + 1.0f;
                float Kx = __expf(-inv2tau2 * d0 * d0);
                float Rx = __expf(aD * (2.0f * d0 - DLT));
                #pragma unroll
                for (int g2 = 0; g2 < 4; ++g2) {
                    float K0 = Kx; Kx *= Rx; Rx *= Cc;
                    float K1 = Kx; Kx *= Rx; Rx *= Cc;
                    sKu2[nl][kk][g2] = make_float2(K0, K1);
                }
                float d0v = v + 1.0f;
                float Kv2 = __expf(-inv2tau2 * d0v * d0v);
                float Rv = __expf(aD * (2.0f * d0v - DLT));
                #pragma unroll
                for (int g = 0; g < GG; ++g) { sKv[nl][kk][g] = Kv2; Kv2 *= Rv; Rv *= Cc; }
            }
        }
        __syncthreads();
        #pragma unroll 8
        for (int n2 = 0; n2 < NC; ++n2) {
            float2 aa = sAA[n2][warp];
            float kvh = sKv[n2][warp][hh];
            float2 ku = sKu2[n2][warp][w02];
            u64 kup = packpair(ku.x, ku.y);
            float tA = aa.x * kvh, tS = aa.y * kvh;
            ffma2(accA, pack2(tA), kup);
            ffma2(accS, pack2(tS), kup);
        }
        __syncthreads();
    }
    float acc00, acc01, acc10, acc11;
    unpack2(acc00, acc01, accA);
    unpack2(acc10, acc11, accS);
    size_t base = ((size_t)((b * KK + warp) * TT + t)) * 128;
    g_splat[base + px0]          = acc00;
    g_splat[base + px0 + 1]      = acc01;
    g_splat[base + 64 + px0]     = acc10;
    g_splat[base + 64 + px0 + 1] = acc11;
}

// ---------------- kernel 2: PERSISTENT CNN — both convs on tensor cores ----
// 256 threads = 8 warps, 4 tiles per iteration, grid 444 (3 blocks/SM).
// Fragments built in-block from w1/w2 during one-time staging (no prep kernel).
#define SM_RED   0       // 16
#define SM_B1    16      // 32
#define SM_B2    48      // 32
#define SM_FC    80      // 32
#define SM_FCB   112     // 1 (+3 pad)
#define SM_IN    116     // [2 buf][4 tiles][2 ch][100] fp32 = 1600
#define SM_H1    1716    // [4 tiles][4 icg][100 px][8 ch] fp16 = 6400 f32
#define SM_BF    8116    // 4608 u32 (conv2 B fragments)
#define SM_B1F   12724   // 1024 u32 (conv1 B fragments)
#define SM_A     13748   // conv1 A buffer: [4 kchunk][256 row] x 16B = 4096 f32
#define SMEM_FLOATS 17844
#define CNN_SMEM_BYTES (SMEM_FLOATS * 4)
#define QUADS (BB * KK * TT / 4)   // 6144
#define CNN_GRID 444

__global__ __launch_bounds__(256, 3) void cnn_kernel(
    const float* __restrict__ w1, const float* __restrict__ b1g,
    const float* __restrict__ w2, const float* __restrict__ b2g,
    const float* __restrict__ fcw, const float* __restrict__ fcb,
    float* __restrict__ out) {
    extern __shared__ float sm[];
    uint32_t* smu = (uint32_t*)sm;
    int tid = threadIdx.x;
    int warp = tid >> 5, lane = tid & 31;
    int tj = tid >> 6;               // tile 0..3 for im2col pixel role
    int p = tid & 63;
    int x = p & 7, y = p >> 3;

    // ---- one-time staging: zero IN+H1 and A chunk3; BUILD fragments ----
    for (int i = tid; i < 8000; i += 256) sm[SM_IN + i] = 0.0f;      // IN(2) + H1
    for (int i = tid; i < 1024; i += 256) sm[SM_A + 3072 + i] = 0.0f; // A chunk3
    // conv2 B fragments (single fp16), uint2 layout; GEMM k = j*32 + ic
    for (int i = tid; i < 4608; i += 256) {
        int r = i & 1;
        int f = i >> 1;
        int bl = f & 31;
        int n8 = (f >> 5) & 3;
        int ks = f >> 7;                 // 0..17
        int oc = n8 * 8 + (bl >> 2);
        int k0 = ks * 16 + (bl & 3) * 2 + r * 8;
        uint32_t pk = 0;
        #pragma unroll
        for (int e = 0; e < 2; ++e) {
            int k = k0 + e;
            int j = k / 32, ic = k % 32;
            float w = w2[oc * 288 + ic * 9 + j];
            unsigned short bits = __half_as_ushort(__float2half_rn(w));
            pk |= (uint32_t)bits << (16 * e);
        }
        smu[SM_BF + i] = pk;
    }
    // conv1 B fragments: GEMM k = c*9 + j (18 real, pad to 32 with zeros)
    for (int i = tid; i < 1024; i += 256) {
        int r = i & 1;
        int f = i >> 1;
        int bl = f & 31;
        int n8 = (f >> 5) & 3;
        int ks = f >> 7;                 // 0..1
        int oc = n8 * 8 + (bl >> 2);
        int k0 = ks * 16 + (bl & 3) * 2 + r * 8;
        uint32_t pk = 0;
        #pragma unroll
        for (int e = 0; e < 2; ++e) {
            int k = k0 + e;
            float w = (k < 18) ? w1[oc * 18 + k] : 0.0f;
            unsigned short bits = __half_as_ushort(__float2half_rn(w));
            pk |= (uint32_t)bits << (16 * e);
        }
        smu[SM_B1F + i] = pk;
    }
    if (tid < 32) {
        sm[SM_B1 + tid] = b1g[tid];
        sm[SM_B2 + tid] = b2g[tid];
        sm[SM_FC + tid] = fcw[tid];
    }
    if (tid == 0) sm[SM_FCB] = fcb[0];

    // IN staging geometry for this thread's two elements (i = tid, tid+256)
    int st_tt0 = tid >> 7, st_e0 = tid & 127;
    int st_ch0 = st_e0 >> 6, st_pp0 = st_e0 & 63;
    int st_dst0 = (st_tt0 * 2 + st_ch0) * 100 + ((st_pp0 >> 3) + 1) * 10 + (st_pp0 & 7) + 1;
    int i1 = tid + 256;
    int st_tt1 = i1 >> 7, st_e1 = i1 & 127;
    int st_ch1 = st_e1 >> 6, st_pp1 = st_e1 & 63;
    int st_dst1 = (st_tt1 * 2 + st_ch1) * 100 + ((st_pp1 >> 3) + 1) * 10 + (st_pp1 & 7) + 1;

    // MMA warp geometry (shared by conv1 and conv2)
    int wtj = warp >> 1, whalf = warp & 1;     // conv2: tile 0..3, half 0/1
    int mat = lane >> 3;
    int rl = ((mat & 1) << 3) | (lane & 7);
    int kseg = mat >> 1;
    uint32_t h1_addr = smem_u32(sm + SM_H1);
    uint32_t a_addr = smem_u32(sm + SM_A);
    int py0 = (whalf * 32 + rl) >> 3,       px0_ = (whalf * 32 + rl) & 7;
    int py1 = (whalf * 32 + 16 + rl) >> 3,  px1_ = (whalf * 32 + 16 + rl) & 7;
    const uint2* bfr2 = (const uint2*)(sm + SM_BF);
    const uint2* b1f2 = (const uint2*)(sm + SM_B1F);
    uint32_t* h1u = (uint32_t*)(sm + SM_H1);
    __syncthreads();

    // ---- prologue: stage first quad into IN buf 0 ----
    int quad = blockIdx.x;
    if (quad < QUADS) {
        float r0 = g_splat[(size_t)quad * 512 + tid];
        float r1 = g_splat[(size_t)quad * 512 + tid + 256];
        sm[SM_IN + st_dst0] = r0;
        sm[SM_IN + st_dst1] = r1;
    }
    __syncthreads();
    int buf = 0;

    while (quad < QUADS) {
        int tile0 = quad * 4;
        int nq = quad + CNN_GRID;
        int inb = SM_IN + buf * 800;

        // ---- conv1 im2col: each thread packs its pixel's 18 k-values ----
        {
            float v[18];
            #pragma unroll
            for (int c = 0; c < 2; ++c)
                #pragma unroll
                for (int jy = 0; jy < 3; ++jy)
                    #pragma unroll
                    for (int jx = 0; jx < 3; ++jx)
                        v[c * 9 + jy * 3 + jx] =
                            sm[inb + (tj * 2 + c) * 100 + (y + jy) * 10 + (x + jx)];
            uint32_t kv[9];
            #pragma unroll
            for (int q = 0; q < 9; ++q) CVTPACK_F16(kv[q], v[2 * q], v[2 * q + 1]);
            ((uint4*)(sm + SM_A))[tid]        = make_uint4(kv[0], kv[1], kv[2], kv[3]);
            ((uint4*)(sm + SM_A + 1024))[tid] = make_uint4(kv[4], kv[5], kv[6], kv[7]);
            ((uint4*)(sm + SM_A + 2048))[tid] = make_uint4(kv[8], 0u, 0u, 0u);
        }
        __syncwarp();

        // ---- prefetch next quad's splat data ----
        float pf0 = 0.0f, pf1 = 0.0f;
        if (nq < QUADS) {
            pf0 = g_splat[(size_t)nq * 512 + tid];
            pf1 = g_splat[(size_t)nq * 512 + tid + 256];
        }

        // ---- conv1 MMA (warp reads its own threads' A rows) ----
        {
            float c1[2][4][4];
            #pragma unroll
            for (int mt = 0; mt < 2; ++mt)
                #pragma unroll
                for (int n8 = 0; n8 < 4; ++n8)
                    #pragma unroll
                    for (int e = 0; e < 4; ++e) c1[mt][n8][e] = 0.0f;
            #pragma unroll
            for (int mt = 0; mt < 2; ++mt)
                #pragma unroll
                for (int ks = 0; ks < 2; ++ks) {
                    uint32_t af[4];
                    uint32_t ad = a_addr + (ks * 2 + kseg) * 4096
                                + (warp * 32 + mt * 16 + rl) * 16;
                    LDMATRIX_X4(af[0], af[1], af[2], af[3], ad);
                    #pragma unroll
                    for (int n8 = 0; n8 < 4; ++n8) {
                        uint2 bv = b1f2[(ks * 4 + n8) * 32 + lane];
                        MMA16816(c1[mt][n8], af, bv.x, bv.y);
                    }
                }
            // bias + GELU + pack to H1
            #pragma unroll
            for (int mt = 0; mt < 2; ++mt) {
                int rb = warp * 32 + mt * 16 + (lane >> 2);
                #pragma unroll
                for (int half = 0; half < 2; ++half) {
                    int r = rb + half * 8;
                    int tile = r >> 6, px = r & 63;
                    int ppx = ((px >> 3) + 1) * 10 + (px & 7) + 1;
                    #pragma unroll
                    for (int n8 = 0; n8 < 4; ++n8) {
                        int c0 = n8 * 8 + (lane & 3) * 2;
                        float g0 = gelu_fast(c1[mt][n8][half * 2]     + sm[SM_B1 + c0]);
                        float g1 = gelu_fast(c1[mt][n8][half * 2 + 1] + sm[SM_B1 + c0 + 1]);
                        uint32_t pr; CVTPACK_F16(pr, g0, g1);
                        h1u[((tile * 4 + n8) * 100 + ppx) * 4 + (lane & 3)] = pr;
                    }
                }
            }
        }
        __syncthreads();   // H1 plane ready (cross-warp)

        // ---- conv2 GEMM via fp16 mma.sync, single pass ----
        float cacc[2][4][4];
        #pragma unroll
        for (int mt = 0; mt < 2; ++mt)
            #pragma unroll
            for (int n8 = 0; n8 < 4; ++n8)
                #pragma unroll
                for (int e = 0; e < 4; ++e) cacc[mt][n8][e] = 0.0f;

        #pragma unroll 1
        for (int j = 0; j < 9; ++j) {
            int dy2 = j / 3, dx2 = j - dy2 * 3;
            int pix0 = (py0 + dy2) * 10 + (px0_ + dx2);
            int pix1 = (py1 + dy2) * 10 + (px1_ + dx2);
            #pragma unroll
            for (int ksg = 0; ksg < 2; ++ksg) {
                uint32_t ah0[4], ah1[4];
                int plane = (wtj * 4 + ksg * 2 + kseg) * 100;
                uint32_t a0 = h1_addr + (plane + pix0) * 16;
                uint32_t a1 = h1_addr + (plane + pix1) * 16;
                LDMATRIX_X4(ah0[0], ah0[1], ah0[2], ah0[3], a0);
                LDMATRIX_X4(ah1[0], ah1[1], ah1[2], ah1[3], a1);
                #pragma unroll
                for (int n8 = 0; n8 < 4; ++n8) {
                    uint2 Bv = bfr2[((2 * j + ksg) * 4 + n8) * 32 + lane];
                    MMA16816(cacc[0][n8], ah0, Bv.x, Bv.y);
                    MMA16816(cacc[1][n8], ah1, Bv.x, Bv.y);
                }
            }
        }

        // ---- epilogue: bias + GELU + fc dot, warp reduce ----
        float s = 0.0f;
        #pragma unroll
        for (int n8 = 0; n8 < 4; ++n8) {
            int oc0 = n8 * 8 + (lane & 3) * 2;
            float bb0 = sm[SM_B2 + oc0], bb1 = sm[SM_B2 + oc0 + 1];
            float ff0 = sm[SM_FC + oc0], ff1 = sm[SM_FC + oc0 + 1];
            #pragma unroll
            for (int mt = 0; mt < 2; ++mt) {
                s = fmaf(gelu_fast(cacc[mt][n8][0] + bb0), ff0, s);
                s = fmaf(gelu_fast(cacc[mt][n8][1] + bb1), ff1, s);
                s = fmaf(gelu_fast(cacc[mt][n8][2] + bb0), ff0, s);
                s = fmaf(gelu_fast(cacc[mt][n8][3] + bb1), ff1, s);
            }
        }
        #pragma unroll
        for (int off = 16; off > 0; off >>= 1)
            s += __shfl_xor_sync(0xffffffffu, s, off);
        if (lane == 0) sm[SM_RED + warp] = s;

        // stage next quad into the other IN buffer (before the barrier)
        int onb = SM_IN + (buf ^ 1) * 800;
        sm[onb + st_dst0] = pf0;
        sm[onb + st_dst1] = pf1;
        __syncthreads();   // RED + IN[buf^1] ready; H1/A reads done

        if (tid < 4) {
            float v = sm[SM_RED + tid * 2] + sm[SM_RED + tid * 2 + 1];
            v = v * (1.0f / 64.0f) + sm[SM_FCB];
            int tile = tile0 + tid;
            int b = tile / (KK * TT);
            int rem = tile - b * (KK * TT);
            int k = rem / TT;
            int t = rem - k * TT;
            out[(b * TT + t) * KK + k] = v;
        }
        buf ^= 1;
        quad = nq;
    }
}

// ---------------- launch ----------------
extern "C" void kernel_launch(void* const* d_in, const int* in_sizes, int n_in,
                              void* d_out, int out_size) {
    const float* mu        = (const float*)d_in[0];
    const float* sigma0    = (const float*)d_in[1];
    const float* sigma_vel = (const float*)d_in[2];
    const float* amplitude = (const float*)d_in[3];
    const float* sh_base   = (const float*)d_in[4];
    const float* sh_vel    = (const float*)d_in[5];
    const float* p0        = (const float*)d_in[6];
    const float* p_vel     = (const float*)d_in[7];
    const float* tau_raw   = (const float*)d_in[8];
    const float* gam_raw   = (const float*)d_in[9];
    const float* limb_ra   = (const float*)d_in[10];
    const float* limb_la   = (const float*)d_in[11];
    const float* limb_ll   = (const float*)d_in[12];
    const float* chest     = (const float*)d_in[13];
    const float* conv1_w   = (const float*)d_in[14];
    const float* conv1_b   = (const float*)d_in[15];
    const float* conv2_w   = (const float*)d_in[16];
    const float* conv2_b   = (const float*)d_in[17];
    const float* fc_w      = (const float*)d_in[18];
    const float* fc_b      = (const float*)d_in[19];
    float* out = (float*)d_out;

    splat_kernel<<<dim3(TT, BB), 384>>>(mu, sigma0, sigma_vel, amplitude,
                                        sh_base, sh_vel, p0, p_vel, tau_raw, gam_raw,
                                        limb_ra, limb_la, limb_ll, chest);
    cudaFuncSetAttribute(cnn_kernel, cudaFuncAttributeMaxDynamicSharedMemorySize,
                         CNN_SMEM_BYTES);
    cnn_kernel<<<CNN_GRID, 256, CNN_SMEM_BYTES>>>(conv1_w, conv1_b, conv2_w, conv2_b,
                                                  fc_w, fc_b, out);
}

// round 15
// speedup vs baseline: 1.5985x; 1.5985x over previous
#include <cuda_runtime.h>
#include <cuda_bf16.h>
#include <cuda_fp16.h>
#include <math.h>
#include <stdint.h>

// Problem dims (fixed by the dataset)
#define BB 4
#define NN 96
#define TT 512
#define KK 12
#define GG 8

typedef unsigned long long u64;

// ---------------- device scratch (no cudaMalloc allowed) ----------------
__device__ float g_splat[(size_t)BB * KK * TT * 128];     // (B,K,T,2,8,8)
// conv2 B fragments (single fp16): frag f = (ks*4+n8)*32+lane holds
// uint32s [2f, 2f+1] = {b_r0, b_r1}
__device__ __align__(16) uint32_t g_bfrag[4608];
// conv1 B fragments (fp16, K=18 padded to 32): frag f = (ks*4+n8)*32+lane
__device__ __align__(16) uint32_t g_b1frag[1024];

// ---------------- small helpers ----------------
__device__ __forceinline__ float softplusf(float x) {
    return (x > 20.0f) ? x : log1pf(expf(x));
}
__device__ __forceinline__ float softplus_fast(float x) {
    return (x > 20.0f) ? x : __logf(1.0f + __expf(x));
}
__device__ __forceinline__ float tanh_fast(float x) {
    float xc = fminf(fmaxf(x, -15.0f), 15.0f);
    float t = __expf(2.0f * xc);
    return (t - 1.0f) * __fdividef(1.0f, t + 1.0f);
}
// Pade [5/4] tanh, valid |x|<=1
__device__ __forceinline__ float tanh_pade(float x) {
    float x2 = x * x;
    float p = fmaf(fmaf(x2, 1.0f, 105.0f), x2, 945.0f);
    float q = fmaf(fmaf(15.0f, x2, 420.0f), x2, 945.0f);
    return __fdividef(x * p, q);
}
__device__ __forceinline__ float acos_fast01(float c) {
    float p = sqrtf(fmaxf(1.0f - c, 0.0f));
    float poly = fmaf(c, fmaf(c, fmaf(c, -0.0187293f, 0.0742610f), -0.2121144f), 1.5707288f);
    return p * poly;
}
// GELU via 3-term A&S erf (|eps| <= 2.5e-5)
__device__ __forceinline__ float gelu_fast(float x) {
    float ax = fabsf(x);
    float z = ax * 0.70710678118f;
    float t = __fdividef(1.0f, fmaf(0.47047f, z, 1.0f));
    float poly = t * fmaf(t, fmaf(t, 0.7478556f, -0.0958798f), 0.3480242f);
    float e = __expf(-z * z);
    float erfv = fmaf(-poly, e, 1.0f);
    return fmaf(0.5f * ax, erfv, 0.5f * x);
}
__device__ __forceinline__ uint32_t smem_u32(const void* p) {
    uint32_t a;
    asm("{ .reg .u64 t; cvta.to.shared.u64 t, %1; cvt.u32.u64 %0, t; }" : "=r"(a) : "l"(p));
    return a;
}
#define CVTPACK_F16(r, a, b) \
    asm("cvt.rn.f16x2.f32 %0, %2, %1;" : "=r"(r) : "f"(a), "f"(b))
#define LDMATRIX_X4(r0, r1, r2, r3, addr) \
    asm volatile("ldmatrix.sync.aligned.m8n8.x4.shared.b16 {%0,%1,%2,%3}, [%4];" \
                 : "=r"(r0), "=r"(r1), "=r"(r2), "=r"(r3) : "r"(addr))
#define MMA16816(c, a, b0, b1) \
    asm volatile("mma.sync.aligned.m16n8k16.row.col.f32.f16.f16.f32 " \
                 "{%0,%1,%2,%3},{%4,%5,%6,%7},{%8,%9},{%0,%1,%2,%3};" \
                 : "+f"((c)[0]), "+f"((c)[1]), "+f"((c)[2]), "+f"((c)[3]) \
                 : "r"((a)[0]), "r"((a)[1]), "r"((a)[2]), "r"((a)[3]), \
                   "r"(b0), "r"(b1))

// ---------------- kernel 1: splat rasterization (R13 datapath) -------------
// Leads computed in-block; block (0,0) additionally builds the CNN's MMA
// B-fragments into device globals (cnn launches after splat in-stream).
#define NC 32

__global__ __launch_bounds__(384) void splat_kernel(
    const float* __restrict__ mu, const float* __restrict__ sigma0,
    const float* __restrict__ sigma_vel, const float* __restrict__ amplitude,
    const float* __restrict__ sh_base, const float* __restrict__ sh_vel,
    const float* __restrict__ p0, const float* __restrict__ p_vel,
    const float* __restrict__ tau_raw, const float* __restrict__ gam_raw,
    const float* __restrict__ ra, const float* __restrict__ la,
    const float* __restrict__ ll, const float* __restrict__ chest,
    const float* __restrict__ w1, const float* __restrict__ w2) {
    __shared__ float  sLead[KK][18];
    __shared__ float  sPN[NN][16];        // {gauss, ppx, ppy, ppz, invpn, sh_dyn[9]}
    __shared__ float2 sAA[NC][KK];
    __shared__ float  sKu[NC][KK][9];
    __shared__ float  sKv[NC][KK][9];

    int t = blockIdx.x, b = blockIdx.y;
    int tid = threadIdx.x;

    // ---- block (0,0): build CNN MMA fragments (one block only) ----
    if (blockIdx.x == 0 && blockIdx.y == 0) {
        for (int i = tid; i < 4608; i += 384) {
            int r = i & 1;
            int f = i >> 1;
            int bl = f & 31;
            int n8 = (f >> 5) & 3;
            int ks = f >> 7;                 // 0..17
            int oc = n8 * 8 + (bl >> 2);
            int k0 = ks * 16 + (bl & 3) * 2 + r * 8;
            uint32_t pk = 0;
            #pragma unroll
            for (int e = 0; e < 2; ++e) {
                int k = k0 + e;
                int j = k / 32, ic = k % 32;
                float w = w2[oc * 288 + ic * 9 + j];
                unsigned short bits = __half_as_ushort(__float2half_rn(w));
                pk |= (uint32_t)bits << (16 * e);
            }
            g_bfrag[i] = pk;
        }
        for (int i = tid; i < 1024; i += 384) {
            int r = i & 1;
            int f = i >> 1;
            int bl = f & 31;
            int n8 = (f >> 5) & 3;
            int ks = f >> 7;                 // 0..1
            int oc = n8 * 8 + (bl >> 2);
            int k0 = ks * 16 + (bl & 3) * 2 + r * 8;
            uint32_t pk = 0;
            #pragma unroll
            for (int e = 0; e < 2; ++e) {
                int k = k0 + e;
                float w = (k < 18) ? w1[oc * 18 + k] : 0.0f;
                unsigned short bits = __half_as_ushort(__float2half_rn(w));
                pk |= (uint32_t)bits << (16 * e);
            }
            g_b1frag[i] = pk;
        }
    }

    // ---- leads: 12 threads build sLead in-block ----
    if (tid < KK) {
        int k = tid;
        float vx, vy, vz;
        float rax = ra[0], ray = ra[1], raz = ra[2];
        float lax = la[0], lay = la[1], laz = la[2];
        float llx = ll[0], lly = ll[1], llz = ll[2];
        switch (k) {
            case 0: vx = lax - rax; vy = lay - ray; vz = laz - raz; break;
            case 1: vx = llx - rax; vy = lly - ray; vz = llz - raz; break;
            case 2: vx = llx - lax; vy = lly - lay; vz = llz - laz; break;
            case 3: vx = rax - 0.5f * (lax + llx); vy = ray - 0.5f * (lay + lly); vz = raz - 0.5f * (laz + llz); break;
            case 4: vx = lax - 0.5f * (rax + llx); vy = lay - 0.5f * (ray + lly); vz = laz - 0.5f * (raz + llz); break;
            case 5: vx = llx - 0.5f * (rax + lax); vy = lly - 0.5f * (ray + lay); vz = llz - 0.5f * (raz + laz); break;
            default:
                vx = chest[(k - 6) * 3 + 0]; vy = chest[(k - 6) * 3 + 1]; vz = chest[(k - 6) * 3 + 2];
                break;
        }
        float n = sqrtf(vx * vx + vy * vy + vz * vz);
        float d = fmaxf(n, 1e-6f);
        float Lx = vx / d, Ly = vy / d, Lz = vz / d;
        float e1x = 0.0f, e1y = Lz, e1z = -Ly;
        float n1 = sqrtf(e1y * e1y + e1z * e1z);
        if (n1 < 1e-4f) { e1x = -Lz; e1y = 0.0f; e1z = Lx; n1 = sqrtf(e1x * e1x + e1z * e1z); }
        float d1 = fmaxf(n1, 1e-6f);
        e1x /= d1; e1y /= d1; e1z /= d1;
        float e2x = e1y * Lz - e1z * Ly;
        float e2y = e1z * Lx - e1x * Lz;
        float e2z = e1x * Ly - e1y * Lx;
        float n2 = sqrtf(e2x * e2x + e2y * e2y + e2z * e2z);
        float d2 = fmaxf(n2, 1e-6f);
        e2x /= d2; e2y /= d2; e2z /= d2;
        float* o = sLead[k];
        o[0] = Lx; o[1] = Ly; o[2] = Lz;
        o[3] = e1x; o[4] = e1y; o[5] = e1z;
        o[6] = e2x; o[7] = e2y; o[8] = e2z;
        o[9]  = 0.282095f;
        o[10] = -0.488603f * Ly;
        o[11] = 0.488603f * Lz;
        o[12] = -0.488603f * Lx;
        o[13] = 1.092548f * Lx * Ly;
        o[14] = -1.092548f * Ly * Lz;
        o[15] = 0.315392f * (3.0f * Lz * Lz - 1.0f);
        o[16] = -1.092548f * Lx * Lz;
        o[17] = 0.546274f * (Lx * Lx - Ly * Ly);
    }

    float tau = softplusf(tau_raw[0]) + 0.06f;
    float inv2tau2 = 0.5f / (tau * tau);
    float gamma = softplusf(gam_raw[0]) + 1e-6f;
    float tval = (float)t * (1.0f / (float)(TT - 1));
    const float DLT = 2.0f / 7.0f;
    float aD = inv2tau2 * DLT;
    float Cc = __expf(-2.0f * aD * DLT);   // exp recurrence constant

    // ---- phase 0: per-n quantities, computed ONCE (96 threads) ----
    if (tid < NN) {
        int bn = b * NN + tid;
        float dt = tval - mu[bn];
        float sig = softplus_fast(sigma0[bn] + sigma_vel[bn] * dt) + 1e-3f;
        float z = dt * __fdividef(1.0f, sig);
        float gauss = amplitude[bn] * __expf(-0.5f * z * z);
        float prx = p0[bn * 3 + 0] + p_vel[bn * 3 + 0] * dt;
        float pry = p0[bn * 3 + 1] + p_vel[bn * 3 + 1] * dt;
        float prz = p0[bn * 3 + 2] + p_vel[bn * 3 + 2] * dt;
        float nrm = fmaxf(sqrtf(prx * prx + pry * pry + prz * prz), 1e-8f);
        float th = tanh_fast(nrm);
        float sc = th * __fdividef(1.0f, nrm);
        float* o = sPN[tid];
        o[0] = gauss;
        o[1] = prx * sc;
        o[2] = pry * sc;
        o[3] = prz * sc;
        o[4] = __fdividef(1.0f, fmaxf(th, 1e-8f));
        #pragma unroll
        for (int m = 0; m < 9; ++m)
            o[5 + m] = fmaf(sh_vel[bn * 9 + m], dt, sh_base[bn * 9 + m]);
    }

    int warp = tid >> 5, lane = tid & 31;
    int px0 = lane * 2;
    int hh = px0 >> 3, w0 = px0 & 7;
    float acc00 = 0.f, acc01 = 0.f, acc10 = 0.f, acc11 = 0.f;

    int nl = tid / KK, kk = tid - nl * KK;
    __syncthreads();

    for (int c = 0; c < NN / NC; ++c) {
        // ---- phase 1: per-(n,k) ----
        {
            int n = c * NC + nl;
            const float* pn = sPN[n];
            const float* Ld = sLead[kk];
            float gauss = pn[0], ppx = pn[1], ppy = pn[2], ppz = pn[3], invpn = pn[4];
            float u = tanh_pade(ppx * Ld[3] + ppy * Ld[4] + ppz * Ld[5]);
            float v = tanh_pade(ppx * Ld[6] + ppy * Ld[7] + ppz * Ld[8]);
            float cosl = (ppx * Ld[0] + ppy * Ld[1] + ppz * Ld[2]) * invpn;
            float hem = fmaxf(cosl, 0.0f);
            float ccv = fminf(fmaxf(cosl, -1.0f + 1e-6f), 1.0f - 1e-6f);
            float theta = acos_fast01(ccv);
            float weight = hem * __expf(-gamma * theta * theta);
            float A = gauss * weight;
            float shp = 0.0f;
            #pragma unroll
            for (int m = 0; m < 9; ++m)
                shp = fmaf(pn[5 + m], Ld[9 + m], shp);
            sAA[nl][kk] = make_float2(A, A * shp);
            // Gaussian grid via exp recurrence: 2 exp per axis
            {
                float d0 = u + 1.0f;
                float Kx = __expf(-inv2tau2 * d0 * d0);
                float Rx = __expf(aD * (2.0f * d0 - DLT));
                #pragma unroll
                for (int g = 0; g < GG; ++g) { sKu[nl][kk][g] = Kx; Kx *= Rx; Rx *= Cc; }
                float d0v = v + 1.0f;
                float Kv2 = __expf(-inv2tau2 * d0v * d0v);
                float Rv = __expf(aD * (2.0f * d0v - DLT));
                #pragma unroll
                for (int g = 0; g < GG; ++g) { sKv[nl][kk][g] = Kv2; Kv2 *= Rv; Rv *= Cc; }
            }
        }
        __syncthreads();
        #pragma unroll 8
        for (int n2 = 0; n2 < NC; ++n2) {
            float2 aa = sAA[n2][warp];
            float kvh = sKv[n2][warp][hh];
            float ku0 = sKu[n2][warp][w0];
            float ku1 = sKu[n2][warp][w0 + 1];
            float tA = aa.x * kvh, tS = aa.y * kvh;
            acc00 = fmaf(tA, ku0, acc00);
            acc01 = fmaf(tA, ku1, acc01);
            acc10 = fmaf(tS, ku0, acc10);
            acc11 = fmaf(tS, ku1, acc11);
        }
        __syncthreads();
    }
    size_t base = ((size_t)((b * KK + warp) * TT + t)) * 128;
    g_splat[base + px0]          = acc00;
    g_splat[base + px0 + 1]      = acc01;
    g_splat[base + 64 + px0]     = acc10;
    g_splat[base + 64 + px0 + 1] = acc11;
}

// ---------------- kernel 2: PERSISTENT CNN — both convs on tensor cores ----
// (byte-identical datapath to round 13)
#define SM_RED   0       // 16
#define SM_B1    16      // 32
#define SM_B2    48      // 32
#define SM_FC    80      // 32
#define SM_FCB   112     // 1 (+3 pad)
#define SM_IN    116     // [2 buf][4 tiles][2 ch][100] fp32 = 1600
#define SM_H1    1716    // [4 tiles][4 icg][100 px][8 ch] fp16 = 6400 f32
#define SM_BF    8116    // 4608 u32 (conv2 B fragments)
#define SM_B1F   12724   // 1024 u32 (conv1 B fragments)
#define SM_A     13748   // conv1 A buffer: [4 kchunk][256 row] x 16B = 4096 f32
#define SMEM_FLOATS 17844
#define CNN_SMEM_BYTES (SMEM_FLOATS * 4)
#define QUADS (BB * KK * TT / 4)   // 6144
#define CNN_GRID 444

__global__ __launch_bounds__(256, 3) void cnn_kernel(
    const float* __restrict__ b1g, const float* __restrict__ b2g,
    const float* __restrict__ fcw, const float* __restrict__ fcb,
    float* __restrict__ out) {
    extern __shared__ float sm[];
    int tid = threadIdx.x;
    int warp = tid >> 5, lane = tid & 31;
    int tj = tid >> 6;               // tile 0..3 for im2col pixel role
    int p = tid & 63;
    int x = p & 7, y = p >> 3;

    // ---- one-time staging: zero IN+H1 and A chunk3; stage fragments ----
    for (int i = tid; i < 8000; i += 256) sm[SM_IN + i] = 0.0f;      // IN(2) + H1
    for (int i = tid; i < 1024; i += 256) sm[SM_A + 3072 + i] = 0.0f; // A chunk3
    {
        float4* dbf = (float4*)(sm + SM_BF);
        const float4* sbf = (const float4*)g_bfrag;
        for (int i = tid; i < 1152; i += 256) dbf[i] = sbf[i];
        float4* db1 = (float4*)(sm + SM_B1F);
        const float4* sb1 = (const float4*)g_b1frag;
        for (int i = tid; i < 256; i += 256) db1[i] = sb1[i];
    }
    if (tid < 32) {
        sm[SM_B1 + tid] = b1g[tid];
        sm[SM_B2 + tid] = b2g[tid];
        sm[SM_FC + tid] = fcw[tid];
    }
    if (tid == 0) sm[SM_FCB] = fcb[0];

    // IN staging geometry for this thread's two elements (i = tid, tid+256)
    int st_tt0 = tid >> 7, st_e0 = tid & 127;
    int st_ch0 = st_e0 >> 6, st_pp0 = st_e0 & 63;
    int st_dst0 = (st_tt0 * 2 + st_ch0) * 100 + ((st_pp0 >> 3) + 1) * 10 + (st_pp0 & 7) + 1;
    int i1 = tid + 256;
    int st_tt1 = i1 >> 7, st_e1 = i1 & 127;
    int st_ch1 = st_e1 >> 6, st_pp1 = st_e1 & 63;
    int st_dst1 = (st_tt1 * 2 + st_ch1) * 100 + ((st_pp1 >> 3) + 1) * 10 + (st_pp1 & 7) + 1;

    // MMA warp geometry (shared by conv1 and conv2)
    int wtj = warp >> 1, whalf = warp & 1;     // conv2: tile 0..3, half 0/1
    int mat = lane >> 3;
    int rl = ((mat & 1) << 3) | (lane & 7);
    int kseg = mat >> 1;
    uint32_t h1_addr = smem_u32(sm + SM_H1);
    uint32_t a_addr = smem_u32(sm + SM_A);
    int py0 = (whalf * 32 + rl) >> 3,       px0_ = (whalf * 32 + rl) & 7;
    int py1 = (whalf * 32 + 16 + rl) >> 3,  px1_ = (whalf * 32 + 16 + rl) & 7;
    const uint2* bfr2 = (const uint2*)(sm + SM_BF);
    const uint2* b1f2 = (const uint2*)(sm + SM_B1F);
    uint32_t* h1u = (uint32_t*)(sm + SM_H1);
    __syncthreads();

    // ---- prologue: stage first quad into IN buf 0 ----
    int quad = blockIdx.x;
    if (quad < QUADS) {
        float r0 = g_splat[(size_t)quad * 512 + tid];
        float r1 = g_splat[(size_t)quad * 512 + tid + 256];
        sm[SM_IN + st_dst0] = r0;
        sm[SM_IN + st_dst1] = r1;
    }
    __syncthreads();
    int buf = 0;

    while (quad < QUADS) {
        int tile0 = quad * 4;
        int nq = quad + CNN_GRID;
        int inb = SM_IN + buf * 800;

        // ---- conv1 im2col: each thread packs its pixel's 18 k-values ----
        {
            float v[18];
            #pragma unroll
            for (int c = 0; c < 2; ++c)
                #pragma unroll
                for (int jy = 0; jy < 3; ++jy)
                    #pragma unroll
                    for (int jx = 0; jx < 3; ++jx)
                        v[c * 9 + jy * 3 + jx] =
                            sm[inb + (tj * 2 + c) * 100 + (y + jy) * 10 + (x + jx)];
            uint32_t kv[9];
            #pragma unroll
            for (int q = 0; q < 9; ++q) CVTPACK_F16(kv[q], v[2 * q], v[2 * q + 1]);
            ((uint4*)(sm + SM_A))[tid]        = make_uint4(kv[0], kv[1], kv[2], kv[3]);
            ((uint4*)(sm + SM_A + 1024))[tid] = make_uint4(kv[4], kv[5], kv[6], kv[7]);
            ((uint4*)(sm + SM_A + 2048))[tid] = make_uint4(kv[8], 0u, 0u, 0u);
        }
        __syncwarp();

        // ---- prefetch next quad's splat data ----
        float pf0 = 0.0f, pf1 = 0.0f;
        if (nq < QUADS) {
            pf0 = g_splat[(size_t)nq * 512 + tid];
            pf1 = g_splat[(size_t)nq * 512 + tid + 256];
        }

        // ---- conv1 MMA (warp reads its own threads' A rows) ----
        {
            float c1[2][4][4];
            #pragma unroll
            for (int mt = 0; mt < 2; ++mt)
                #pragma unroll
                for (int n8 = 0; n8 < 4; ++n8)
                    #pragma unroll
                    for (int e = 0; e < 4; ++e) c1[mt][n8][e] = 0.0f;
            #pragma unroll
            for (int mt = 0; mt < 2; ++mt)
                #pragma unroll
                for (int ks = 0; ks < 2; ++ks) {
                    uint32_t af[4];
                    uint32_t ad = a_addr + (ks * 2 + kseg) * 4096
                                + (warp * 32 + mt * 16 + rl) * 16;
                    LDMATRIX_X4(af[0], af[1], af[2], af[3], ad);
                    #pragma unroll
                    for (int n8 = 0; n8 < 4; ++n8) {
                        uint2 bv = b1f2[(ks * 4 + n8) * 32 + lane];
                        MMA16816(c1[mt][n8], af, bv.x, bv.y);
                    }
                }
            // bias + GELU + pack to H1
            #pragma unroll
            for (int mt = 0; mt < 2; ++mt) {
                int rb = warp * 32 + mt * 16 + (lane >> 2);
                #pragma unroll
                for (int half = 0; half < 2; ++half) {
                    int r = rb + half * 8;
                    int tile = r >> 6, px = r & 63;
                    int ppx = ((px >> 3) + 1) * 10 + (px & 7) + 1;
                    #pragma unroll
                    for (int n8 = 0; n8 < 4; ++n8) {
                        int c0 = n8 * 8 + (lane & 3) * 2;
                        float g0 = gelu_fast(c1[mt][n8][half * 2]     + sm[SM_B1 + c0]);
                        float g1 = gelu_fast(c1[mt][n8][half * 2 + 1] + sm[SM_B1 + c0 + 1]);
                        uint32_t pr; CVTPACK_F16(pr, g0, g1);
                        h1u[((tile * 4 + n8) * 100 + ppx) * 4 + (lane & 3)] = pr;
                    }
                }
            }
        }
        __syncthreads();   // H1 plane ready (cross-warp)

        // ---- conv2 GEMM via fp16 mma.sync, single pass ----
        float cacc[2][4][4];
        #pragma unroll
        for (int mt = 0; mt < 2; ++mt)
            #pragma unroll
            for (int n8 = 0; n8 < 4; ++n8)
                #pragma unroll
                for (int e = 0; e < 4; ++e) cacc[mt][n8][e] = 0.0f;

        #pragma unroll 1
        for (int j = 0; j < 9; ++j) {
            int dy2 = j / 3, dx2 = j - dy2 * 3;
            int pix0 = (py0 + dy2) * 10 + (px0_ + dx2);
            int pix1 = (py1 + dy2) * 10 + (px1_ + dx2);
            #pragma unroll
            for (int ksg = 0; ksg < 2; ++ksg) {
                uint32_t ah0[4], ah1[4];
                int plane = (wtj * 4 + ksg * 2 + kseg) * 100;
                uint32_t a0 = h1_addr + (plane + pix0) * 16;
                uint32_t a1 = h1_addr + (plane + pix1) * 16;
                LDMATRIX_X4(ah0[0], ah0[1], ah0[2], ah0[3], a0);
                LDMATRIX_X4(ah1[0], ah1[1], ah1[2], ah1[3], a1);
                #pragma unroll
                for (int n8 = 0; n8 < 4; ++n8) {
                    uint2 Bv = bfr2[((2 * j + ksg) * 4 + n8) * 32 + lane];
                    MMA16816(cacc[0][n8], ah0, Bv.x, Bv.y);
                    MMA16816(cacc[1][n8], ah1, Bv.x, Bv.y);
                }
            }
        }

        // ---- epilogue: bias + GELU + fc dot, warp reduce ----
        float s = 0.0f;
        #pragma unroll
        for (int n8 = 0; n8 < 4; ++n8) {
            int oc0 = n8 * 8 + (lane & 3) * 2;
            float bb0 = sm[SM_B2 + oc0], bb1 = sm[SM_B2 + oc0 + 1];
            float ff0 = sm[SM_FC + oc0], ff1 = sm[SM_FC + oc0 + 1];
            #pragma unroll
            for (int mt = 0; mt < 2; ++mt) {
                s = fmaf(gelu_fast(cacc[mt][n8][0] + bb0), ff0, s);
                s = fmaf(gelu_fast(cacc[mt][n8][1] + bb1), ff1, s);
                s = fmaf(gelu_fast(cacc[mt][n8][2] + bb0), ff0, s);
                s = fmaf(gelu_fast(cacc[mt][n8][3] + bb1), ff1, s);
            }
        }
        #pragma unroll
        for (int off = 16; off > 0; off >>= 1)
            s += __shfl_xor_sync(0xffffffffu, s, off);
        if (lane == 0) sm[SM_RED + warp] = s;

        // stage next quad into the other IN buffer (before the barrier)
        int onb = SM_IN + (buf ^ 1) * 800;
        sm[onb + st_dst0] = pf0;
        sm[onb + st_dst1] = pf1;
        __syncthreads();   // RED + IN[buf^1] ready; H1/A reads done

        if (tid < 4) {
            float v = sm[SM_RED + tid * 2] + sm[SM_RED + tid * 2 + 1];
            v = v * (1.0f / 64.0f) + sm[SM_FCB];
            int tile = tile0 + tid;
            int b = tile / (KK * TT);
            int rem = tile - b * (KK * TT);
            int k = rem / TT;
            int t = rem - k * TT;
            out[(b * TT + t) * KK + k] = v;
        }
        buf ^= 1;
        quad = nq;
    }
}

// ---------------- launch ----------------
extern "C" void kernel_launch(void* const* d_in, const int* in_sizes, int n_in,
                              void* d_out, int out_size) {
    const float* mu        = (const float*)d_in[0];
    const float* sigma0    = (const float*)d_in[1];
    const float* sigma_vel = (const float*)d_in[2];
    const float* amplitude = (const float*)d_in[3];
    const float* sh_base   = (const float*)d_in[4];
    const float* sh_vel    = (const float*)d_in[5];
    const float* p0        = (const float*)d_in[6];
    const float* p_vel     = (const float*)d_in[7];
    const float* tau_raw   = (const float*)d_in[8];
    const float* gam_raw   = (const float*)d_in[9];
    const float* limb_ra   = (const float*)d_in[10];
    const float* limb_la   = (const float*)d_in[11];
    const float* limb_ll   = (const float*)d_in[12];
    const float* chest     = (const float*)d_in[13];
    const float* conv1_w   = (const float*)d_in[14];
    const float* conv1_b   = (const float*)d_in[15];
    const float* conv2_w   = (const float*)d_in[16];
    const float* conv2_b   = (const float*)d_in[17];
    const float* fc_w      = (const float*)d_in[18];
    const float* fc_b      = (const float*)d_in[19];
    float* out = (float*)d_out;

    splat_kernel<<<dim3(TT, BB), 384>>>(mu, sigma0, sigma_vel, amplitude,
                                        sh_base, sh_vel, p0, p_vel, tau_raw, gam_raw,
                                        limb_ra, limb_la, limb_ll, chest,
                                        conv1_w, conv2_w);
    cudaFuncSetAttribute(cnn_kernel, cudaFuncAttributeMaxDynamicSharedMemorySize,
                         CNN_SMEM_BYTES);
    cnn_kernel<<<CNN_GRID, 256, CNN_SMEM_BYTES>>>(conv1_b, conv2_b, fc_w, fc_b, out);
}

// round 16
// speedup vs baseline: 1.7925x; 1.1214x over previous
#include <cuda_runtime.h>
#include <cuda_bf16.h>
#include <cuda_fp16.h>
#include <math.h>
#include <stdint.h>

// Problem dims (fixed by the dataset)
#define BB 4
#define NN 96
#define TT 512
#define KK 12
#define GG 8

typedef unsigned long long u64;

// ---------------- device scratch (no cudaMalloc allowed) ----------------
__device__ float g_splat[(size_t)BB * KK * TT * 128];     // (B,K,T,2,8,8)
// conv2 B fragments (single fp16): frag f = (ks*4+n8)*32+lane holds
// uint32s [2f, 2f+1] = {b_r0, b_r1}
__device__ __align__(16) uint32_t g_bfrag[4608];
// conv1 B fragments (fp16, K=18 padded to 32): frag f = (ks*4+n8)*32+lane
__device__ __align__(16) uint32_t g_b1frag[1024];

// ---------------- small helpers ----------------
__device__ __forceinline__ float softplusf(float x) {
    return (x > 20.0f) ? x : log1pf(expf(x));
}
__device__ __forceinline__ float softplus_fast(float x) {
    return (x > 20.0f) ? x : __logf(1.0f + __expf(x));
}
__device__ __forceinline__ float tanh_fast(float x) {
    float xc = fminf(fmaxf(x, -15.0f), 15.0f);
    float t = __expf(2.0f * xc);
    return (t - 1.0f) * __fdividef(1.0f, t + 1.0f);
}
// Pade [5/4] tanh, valid |x|<=1
__device__ __forceinline__ float tanh_pade(float x) {
    float x2 = x * x;
    float p = fmaf(fmaf(x2, 1.0f, 105.0f), x2, 945.0f);
    float q = fmaf(fmaf(15.0f, x2, 420.0f), x2, 945.0f);
    return __fdividef(x * p, q);
}
__device__ __forceinline__ float acos_fast01(float c) {
    float p = sqrtf(fmaxf(1.0f - c, 0.0f));
    float poly = fmaf(c, fmaf(c, fmaf(c, -0.0187293f, 0.0742610f), -0.2121144f), 1.5707288f);
    return p * poly;
}
// GELU via 3-term A&S erf (|eps| <= 2.5e-5) — used where errors amplify (conv1)
__device__ __forceinline__ float gelu_fast(float x) {
    float ax = fabsf(x);
    float z = ax * 0.70710678118f;
    float t = __fdividef(1.0f, fmaf(0.47047f, z, 1.0f));
    float poly = t * fmaf(t, fmaf(t, 0.7478556f, -0.0958798f), 0.3480242f);
    float e = __expf(-z * z);
    float erfv = fmaf(-poly, e, 1.0f);
    return fmaf(0.5f * ax, erfv, 0.5f * x);
}
__device__ __forceinline__ uint32_t smem_u32(const void* p) {
    uint32_t a;
    asm("{ .reg .u64 t; cvta.to.shared.u64 t, %1; cvt.u32.u64 %0, t; }" : "=r"(a) : "l"(p));
    return a;
}
#define CVTPACK_F16(r, a, b) \
    asm("cvt.rn.f16x2.f32 %0, %2, %1;" : "=r"(r) : "f"(a), "f"(b))
#define LDMATRIX_X4(r0, r1, r2, r3, addr) \
    asm volatile("ldmatrix.sync.aligned.m8n8.x4.shared.b16 {%0,%1,%2,%3}, [%4];" \
                 : "=r"(r0), "=r"(r1), "=r"(r2), "=r"(r3) : "r"(addr))
#define MMA16816(c, a, b0, b1) \
    asm volatile("mma.sync.aligned.m16n8k16.row.col.f32.f16.f16.f32 " \
                 "{%0,%1,%2,%3},{%4,%5,%6,%7},{%8,%9},{%0,%1,%2,%3};" \
                 : "+f"((c)[0]), "+f"((c)[1]), "+f"((c)[2]), "+f"((c)[3]) \
                 : "r"((a)[0]), "r"((a)[1]), "r"((a)[2]), "r"((a)[3]), \
                   "r"(b0), "r"(b1))
// f16x2 math
#define H2MUL(d, a, b) \
    asm("mul.f16x2 %0, %1, %2;" : "=r"(d) : "r"(a), "r"(b))
#define H2FMA(d, a, b, c) \
    asm("fma.rn.f16x2 %0, %1, %2, %3;" : "=r"(d) : "r"(a), "r"(b), "r"(c))
#define H2TANH(d, a) \
    asm("tanh.approx.f16x2 %0, %1;" : "=r"(d) : "r"(a))

// ---------------- kernel 1: splat rasterization (R13 datapath) -------------
// Leads computed in-block; block (0,0) additionally builds the CNN's MMA
// B-fragments into device globals (cnn launches after splat in-stream).
#define NC 32

__global__ __launch_bounds__(384) void splat_kernel(
    const float* __restrict__ mu, const float* __restrict__ sigma0,
    const float* __restrict__ sigma_vel, const float* __restrict__ amplitude,
    const float* __restrict__ sh_base, const float* __restrict__ sh_vel,
    const float* __restrict__ p0, const float* __restrict__ p_vel,
    const float* __restrict__ tau_raw, const float* __restrict__ gam_raw,
    const float* __restrict__ ra, const float* __restrict__ la,
    const float* __restrict__ ll, const float* __restrict__ chest,
    const float* __restrict__ w1, const float* __restrict__ w2) {
    __shared__ float  sLead[KK][18];
    __shared__ float  sPN[NN][16];        // {gauss, ppx, ppy, ppz, invpn, sh_dyn[9]}
    __shared__ float2 sAA[NC][KK];
    __shared__ float2 sKu2[NC][KK][4];    // ku pairs (LDS.64)
    __shared__ float  sKv[NC][KK][9];

    int t = blockIdx.x, b = blockIdx.y;
    int tid = threadIdx.x;

    // ---- block (0,0): build CNN MMA fragments (one block only) ----
    if (blockIdx.x == 0 && blockIdx.y == 0) {
        for (int i = tid; i < 4608; i += 384) {
            int r = i & 1;
            int f = i >> 1;
            int bl = f & 31;
            int n8 = (f >> 5) & 3;
            int ks = f >> 7;                 // 0..17
            int oc = n8 * 8 + (bl >> 2);
            int k0 = ks * 16 + (bl & 3) * 2 + r * 8;
            uint32_t pk = 0;
            #pragma unroll
            for (int e = 0; e < 2; ++e) {
                int k = k0 + e;
                int j = k / 32, ic = k % 32;
                float w = w2[oc * 288 + ic * 9 + j];
                unsigned short bits = __half_as_ushort(__float2half_rn(w));
                pk |= (uint32_t)bits << (16 * e);
            }
            g_bfrag[i] = pk;
        }
        for (int i = tid; i < 1024; i += 384) {
            int r = i & 1;
            int f = i >> 1;
            int bl = f & 31;
            int n8 = (f >> 5) & 3;
            int ks = f >> 7;                 // 0..1
            int oc = n8 * 8 + (bl >> 2);
            int k0 = ks * 16 + (bl & 3) * 2 + r * 8;
            uint32_t pk = 0;
            #pragma unroll
            for (int e = 0; e < 2; ++e) {
                int k = k0 + e;
                float w = (k < 18) ? w1[oc * 18 + k] : 0.0f;
                unsigned short bits = __half_as_ushort(__float2half_rn(w));
                pk |= (uint32_t)bits << (16 * e);
            }
            g_b1frag[i] = pk;
        }
    }

    // ---- leads: 12 threads build sLead in-block ----
    if (tid < KK) {
        int k = tid;
        float vx, vy, vz;
        float rax = ra[0], ray = ra[1], raz = ra[2];
        float lax = la[0], lay = la[1], laz = la[2];
        float llx = ll[0], lly = ll[1], llz = ll[2];
        switch (k) {
            case 0: vx = lax - rax; vy = lay - ray; vz = laz - raz; break;
            case 1: vx = llx - rax; vy = lly - ray; vz = llz - raz; break;
            case 2: vx = llx - lax; vy = lly - lay; vz = llz - laz; break;
            case 3: vx = rax - 0.5f * (lax + llx); vy = ray - 0.5f * (lay + lly); vz = raz - 0.5f * (laz + llz); break;
            case 4: vx = lax - 0.5f * (rax + llx); vy = lay - 0.5f * (ray + lly); vz = laz - 0.5f * (raz + llz); break;
            case 5: vx = llx - 0.5f * (rax + lax); vy = lly - 0.5f * (ray + lay); vz = llz - 0.5f * (raz + laz); break;
            default:
                vx = chest[(k - 6) * 3 + 0]; vy = chest[(k - 6) * 3 + 1]; vz = chest[(k - 6) * 3 + 2];
                break;
        }
        float n = sqrtf(vx * vx + vy * vy + vz * vz);
        float d = fmaxf(n, 1e-6f);
        float Lx = vx / d, Ly = vy / d, Lz = vz / d;
        float e1x = 0.0f, e1y = Lz, e1z = -Ly;
        float n1 = sqrtf(e1y * e1y + e1z * e1z);
        if (n1 < 1e-4f) { e1x = -Lz; e1y = 0.0f; e1z = Lx; n1 = sqrtf(e1x * e1x + e1z * e1z); }
        float d1 = fmaxf(n1, 1e-6f);
        e1x /= d1; e1y /= d1; e1z /= d1;
        float e2x = e1y * Lz - e1z * Ly;
        float e2y = e1z * Lx - e1x * Lz;
        float e2z = e1x * Ly - e1y * Lx;
        float n2 = sqrtf(e2x * e2x + e2y * e2y + e2z * e2z);
        float d2 = fmaxf(n2, 1e-6f);
        e2x /= d2; e2y /= d2; e2z /= d2;
        float* o = sLead[k];
        o[0] = Lx; o[1] = Ly; o[2] = Lz;
        o[3] = e1x; o[4] = e1y; o[5] = e1z;
        o[6] = e2x; o[7] = e2y; o[8] = e2z;
        o[9]  = 0.282095f;
        o[10] = -0.488603f * Ly;
        o[11] = 0.488603f * Lz;
        o[12] = -0.488603f * Lx;
        o[13] = 1.092548f * Lx * Ly;
        o[14] = -1.092548f * Ly * Lz;
        o[15] = 0.315392f * (3.0f * Lz * Lz - 1.0f);
        o[16] = -1.092548f * Lx * Lz;
        o[17] = 0.546274f * (Lx * Lx - Ly * Ly);
    }

    float tau = softplusf(tau_raw[0]) + 0.06f;
    float inv2tau2 = 0.5f / (tau * tau);
    float gamma = softplusf(gam_raw[0]) + 1e-6f;
    float tval = (float)t * (1.0f / (float)(TT - 1));
    const float DLT = 2.0f / 7.0f;
    float aD = inv2tau2 * DLT;
    float Cc = __expf(-2.0f * aD * DLT);   // exp recurrence constant

    // ---- phase 0: per-n quantities, computed ONCE (96 threads) ----
    if (tid < NN) {
        int bn = b * NN + tid;
        float dt = tval - mu[bn];
        float sig = softplus_fast(sigma0[bn] + sigma_vel[bn] * dt) + 1e-3f;
        float z = dt * __fdividef(1.0f, sig);
        float gauss = amplitude[bn] * __expf(-0.5f * z * z);
        float prx = p0[bn * 3 + 0] + p_vel[bn * 3 + 0] * dt;
        float pry = p0[bn * 3 + 1] + p_vel[bn * 3 + 1] * dt;
        float prz = p0[bn * 3 + 2] + p_vel[bn * 3 + 2] * dt;
        float nrm = fmaxf(sqrtf(prx * prx + pry * pry + prz * prz), 1e-8f);
        float th = tanh_fast(nrm);
        float sc = th * __fdividef(1.0f, nrm);
        float* o = sPN[tid];
        o[0] = gauss;
        o[1] = prx * sc;
        o[2] = pry * sc;
        o[3] = prz * sc;
        o[4] = __fdividef(1.0f, fmaxf(th, 1e-8f));
        #pragma unroll
        for (int m = 0; m < 9; ++m)
            o[5 + m] = fmaf(sh_vel[bn * 9 + m], dt, sh_base[bn * 9 + m]);
    }

    int warp = tid >> 5, lane = tid & 31;
    int px0 = lane * 2;
    int hh = px0 >> 3, w0 = px0 & 7;
    int w02 = w0 >> 1;
    float acc00 = 0.f, acc01 = 0.f, acc10 = 0.f, acc11 = 0.f;

    int nl = tid / KK, kk = tid - nl * KK;
    __syncthreads();

    for (int c = 0; c < NN / NC; ++c) {
        // ---- phase 1: per-(n,k) ----
        {
            int n = c * NC + nl;
            const float* pn = sPN[n];
            const float* Ld = sLead[kk];
            float gauss = pn[0], ppx = pn[1], ppy = pn[2], ppz = pn[3], invpn = pn[4];
            float u = tanh_pade(ppx * Ld[3] + ppy * Ld[4] + ppz * Ld[5]);
            float v = tanh_pade(ppx * Ld[6] + ppy * Ld[7] + ppz * Ld[8]);
            float cosl = (ppx * Ld[0] + ppy * Ld[1] + ppz * Ld[2]) * invpn;
            float hem = fmaxf(cosl, 0.0f);
            float ccv = fminf(fmaxf(cosl, -1.0f + 1e-6f), 1.0f - 1e-6f);
            float theta = acos_fast01(ccv);
            float weight = hem * __expf(-gamma * theta * theta);
            float A = gauss * weight;
            float shp = 0.0f;
            #pragma unroll
            for (int m = 0; m < 9; ++m)
                shp = fmaf(pn[5 + m], Ld[9 + m], shp);
            sAA[nl][kk] = make_float2(A, A * shp);
            // Gaussian grid via exp recurrence: 2 exp per axis; ku as pairs
            {
                float d0 = u + 1.0f;
                float Kx = __expf(-inv2tau2 * d0 * d0);
                float Rx = __expf(aD * (2.0f * d0 - DLT));
                #pragma unroll
                for (int g2 = 0; g2 < 4; ++g2) {
                    float K0 = Kx; Kx *= Rx; Rx *= Cc;
                    float K1 = Kx; Kx *= Rx; Rx *= Cc;
                    sKu2[nl][kk][g2] = make_float2(K0, K1);
                }
                float d0v = v + 1.0f;
                float Kv2 = __expf(-inv2tau2 * d0v * d0v);
                float Rv = __expf(aD * (2.0f * d0v - DLT));
                #pragma unroll
                for (int g = 0; g < GG; ++g) { sKv[nl][kk][g] = Kv2; Kv2 *= Rv; Rv *= Cc; }
            }
        }
        __syncthreads();
        #pragma unroll 8
        for (int n2 = 0; n2 < NC; ++n2) {
            float2 aa = sAA[n2][warp];
            float kvh = sKv[n2][warp][hh];
            float2 ku = sKu2[n2][warp][w02];
            float tA = aa.x * kvh, tS = aa.y * kvh;
            acc00 = fmaf(tA, ku.x, acc00);
            acc01 = fmaf(tA, ku.y, acc01);
            acc10 = fmaf(tS, ku.x, acc10);
            acc11 = fmaf(tS, ku.y, acc11);
        }
        __syncthreads();
    }
    size_t base = ((size_t)((b * KK + warp) * TT + t)) * 128;
    g_splat[base + px0]          = acc00;
    g_splat[base + px0 + 1]      = acc01;
    g_splat[base + 64 + px0]     = acc10;
    g_splat[base + 64 + px0 + 1] = acc11;
}

// ---------------- kernel 2: PERSISTENT CNN — both convs on tensor cores ----
// (R13/R15 datapath; epilogue GELU switched to packed f16x2 tanh-form)
#define SM_RED   0       // 16
#define SM_B1    16      // 32
#define SM_B2    48      // 32
#define SM_FC    80      // 32
#define SM_FCB   112     // 1 (+3 pad)
#define SM_IN    116     // [2 buf][4 tiles][2 ch][100] fp32 = 1600
#define SM_H1    1716    // [4 tiles][4 icg][100 px][8 ch] fp16 = 6400 f32
#define SM_BF    8116    // 4608 u32 (conv2 B fragments)
#define SM_B1F   12724   // 1024 u32 (conv1 B fragments)
#define SM_A     13748   // conv1 A buffer: [4 kchunk][256 row] x 16B = 4096 f32
#define SMEM_FLOATS 17844
#define CNN_SMEM_BYTES (SMEM_FLOATS * 4)
#define QUADS (BB * KK * TT / 4)   // 6144
#define CNN_GRID 444

__global__ __launch_bounds__(256, 3) void cnn_kernel(
    const float* __restrict__ b1g, const float* __restrict__ b2g,
    const float* __restrict__ fcw, const float* __restrict__ fcb,
    float* __restrict__ out) {
    extern __shared__ float sm[];
    int tid = threadIdx.x;
    int warp = tid >> 5, lane = tid & 31;
    int tj = tid >> 6;               // tile 0..3 for im2col pixel role
    int p = tid & 63;
    int x = p & 7, y = p >> 3;

    // f16x2 tanh-gelu constants
    uint32_t C0h2, C1h2, Hh2;
    CVTPACK_F16(C0h2, 0.797885f, 0.797885f);
    CVTPACK_F16(C1h2, 0.0356774f, 0.0356774f);
    CVTPACK_F16(Hh2, 0.5f, 0.5f);

    // ---- one-time staging: zero IN+H1 and A chunk3; stage fragments ----
    for (int i = tid; i < 8000; i += 256) sm[SM_IN + i] = 0.0f;      // IN(2) + H1
    for (int i = tid; i < 1024; i += 256) sm[SM_A + 3072 + i] = 0.0f; // A chunk3
    {
        float4* dbf = (float4*)(sm + SM_BF);
        const float4* sbf = (const float4*)g_bfrag;
        for (int i = tid; i < 1152; i += 256) dbf[i] = sbf[i];
        float4* db1 = (float4*)(sm + SM_B1F);
        const float4* sb1 = (const float4*)g_b1frag;
        for (int i = tid; i < 256; i += 256) db1[i] = sb1[i];
    }
    if (tid < 32) {
        sm[SM_B1 + tid] = b1g[tid];
        sm[SM_B2 + tid] = b2g[tid];
        sm[SM_FC + tid] = fcw[tid];
    }
    if (tid == 0) sm[SM_FCB] = fcb[0];

    // IN staging geometry for this thread's two elements (i = tid, tid+256)
    int st_tt0 = tid >> 7, st_e0 = tid & 127;
    int st_ch0 = st_e0 >> 6, st_pp0 = st_e0 & 63;
    int st_dst0 = (st_tt0 * 2 + st_ch0) * 100 + ((st_pp0 >> 3) + 1) * 10 + (st_pp0 & 7) + 1;
    int i1 = tid + 256;
    int st_tt1 = i1 >> 7, st_e1 = i1 & 127;
    int st_ch1 = st_e1 >> 6, st_pp1 = st_e1 & 63;
    int st_dst1 = (st_tt1 * 2 + st_ch1) * 100 + ((st_pp1 >> 3) + 1) * 10 + (st_pp1 & 7) + 1;

    // MMA warp geometry (shared by conv1 and conv2)
    int wtj = warp >> 1, whalf = warp & 1;     // conv2: tile 0..3, half 0/1
    int mat = lane >> 3;
    int rl = ((mat & 1) << 3) | (lane & 7);
    int kseg = mat >> 1;
    uint32_t h1_addr = smem_u32(sm + SM_H1);
    uint32_t a_addr = smem_u32(sm + SM_A);
    int py0 = (whalf * 32 + rl) >> 3,       px0_ = (whalf * 32 + rl) & 7;
    int py1 = (whalf * 32 + 16 + rl) >> 3,  px1_ = (whalf * 32 + 16 + rl) & 7;
    const uint2* bfr2 = (const uint2*)(sm + SM_BF);
    const uint2* b1f2 = (const uint2*)(sm + SM_B1F);
    uint32_t* h1u = (uint32_t*)(sm + SM_H1);
    __syncthreads();

    // ---- prologue: stage first quad into IN buf 0 ----
    int quad = blockIdx.x;
    if (quad < QUADS) {
        float r0 = g_splat[(size_t)quad * 512 + tid];
        float r1 = g_splat[(size_t)quad * 512 + tid + 256];
        sm[SM_IN + st_dst0] = r0;
        sm[SM_IN + st_dst1] = r1;
    }
    __syncthreads();
    int buf = 0;

    while (quad < QUADS) {
        int tile0 = quad * 4;
        int nq = quad + CNN_GRID;
        int inb = SM_IN + buf * 800;

        // ---- conv1 im2col: each thread packs its pixel's 18 k-values ----
        {
            float v[18];
            #pragma unroll
            for (int c = 0; c < 2; ++c)
                #pragma unroll
                for (int jy = 0; jy < 3; ++jy)
                    #pragma unroll
                    for (int jx = 0; jx < 3; ++jx)
                        v[c * 9 + jy * 3 + jx] =
                            sm[inb + (tj * 2 + c) * 100 + (y + jy) * 10 + (x + jx)];
            uint32_t kv[9];
            #pragma unroll
            for (int q = 0; q < 9; ++q) CVTPACK_F16(kv[q], v[2 * q], v[2 * q + 1]);
            ((uint4*)(sm + SM_A))[tid]        = make_uint4(kv[0], kv[1], kv[2], kv[3]);
            ((uint4*)(sm + SM_A + 1024))[tid] = make_uint4(kv[4], kv[5], kv[6], kv[7]);
            ((uint4*)(sm + SM_A + 2048))[tid] = make_uint4(kv[8], 0u, 0u, 0u);
        }
        __syncwarp();

        // ---- prefetch next quad's splat data ----
        float pf0 = 0.0f, pf1 = 0.0f;
        if (nq < QUADS) {
            pf0 = g_splat[(size_t)nq * 512 + tid];
            pf1 = g_splat[(size_t)nq * 512 + tid + 256];
        }

        // ---- conv1 MMA (warp reads its own threads' A rows) ----
        {
            float c1[2][4][4];
            #pragma unroll
            for (int mt = 0; mt < 2; ++mt)
                #pragma unroll
                for (int n8 = 0; n8 < 4; ++n8)
                    #pragma unroll
                    for (int e = 0; e < 4; ++e) c1[mt][n8][e] = 0.0f;
            #pragma unroll
            for (int mt = 0; mt < 2; ++mt)
                #pragma unroll
                for (int ks = 0; ks < 2; ++ks) {
                    uint32_t af[4];
                    uint32_t ad = a_addr + (ks * 2 + kseg) * 4096
                                + (warp * 32 + mt * 16 + rl) * 16;
                    LDMATRIX_X4(af[0], af[1], af[2], af[3], ad);
                    #pragma unroll
                    for (int n8 = 0; n8 < 4; ++n8) {
                        uint2 bv = b1f2[(ks * 4 + n8) * 32 + lane];
                        MMA16816(c1[mt][n8], af, bv.x, bv.y);
                    }
                }
            // bias + GELU (exact) + pack to H1
            #pragma unroll
            for (int mt = 0; mt < 2; ++mt) {
                int rb = warp * 32 + mt * 16 + (lane >> 2);
                #pragma unroll
                for (int half = 0; half < 2; ++half) {
                    int r = rb + half * 8;
                    int tile = r >> 6, px = r & 63;
                    int ppx = ((px >> 3) + 1) * 10 + (px & 7) + 1;
                    #pragma unroll
                    for (int n8 = 0; n8 < 4; ++n8) {
                        int c0 = n8 * 8 + (lane & 3) * 2;
                        float g0 = gelu_fast(c1[mt][n8][half * 2]     + sm[SM_B1 + c0]);
                        float g1 = gelu_fast(c1[mt][n8][half * 2 + 1] + sm[SM_B1 + c0 + 1]);
                        uint32_t pr; CVTPACK_F16(pr, g0, g1);
                        h1u[((tile * 4 + n8) * 100 + ppx) * 4 + (lane & 3)] = pr;
                    }
                }
            }
        }
        __syncthreads();   // H1 plane ready (cross-warp)

        // ---- conv2 GEMM via fp16 mma.sync, single pass ----
        float cacc[2][4][4];
        #pragma unroll
        for (int mt = 0; mt < 2; ++mt)
            #pragma unroll
            for (int n8 = 0; n8 < 4; ++n8)
                #pragma unroll
                for (int e = 0; e < 4; ++e) cacc[mt][n8][e] = 0.0f;

        #pragma unroll 1
        for (int j = 0; j < 9; ++j) {
            int dy2 = j / 3, dx2 = j - dy2 * 3;
            int pix0 = (py0 + dy2) * 10 + (px0_ + dx2);
            int pix1 = (py1 + dy2) * 10 + (px1_ + dx2);
            #pragma unroll
            for (int ksg = 0; ksg < 2; ++ksg) {
                uint32_t ah0[4], ah1[4];
                int plane = (wtj * 4 + ksg * 2 + kseg) * 100;
                uint32_t a0 = h1_addr + (plane + pix0) * 16;
                uint32_t a1 = h1_addr + (plane + pix1) * 16;
                LDMATRIX_X4(ah0[0], ah0[1], ah0[2], ah0[3], a0);
                LDMATRIX_X4(ah1[0], ah1[1], ah1[2], ah1[3], a1);
                #pragma unroll
                for (int n8 = 0; n8 < 4; ++n8) {
                    uint2 Bv = bfr2[((2 * j + ksg) * 4 + n8) * 32 + lane];
                    MMA16816(cacc[0][n8], ah0, Bv.x, Bv.y);
                    MMA16816(cacc[1][n8], ah1, Bv.x, Bv.y);
                }
            }
        }

        // ---- epilogue: bias + packed f16x2 tanh-GELU + fc dot, warp reduce ----
        float s = 0.0f;
        #pragma unroll
        for (int n8 = 0; n8 < 4; ++n8) {
            int oc0 = n8 * 8 + (lane & 3) * 2;
            float bb0 = sm[SM_B2 + oc0], bb1 = sm[SM_B2 + oc0 + 1];
            float ff0 = sm[SM_FC + oc0], ff1 = sm[SM_FC + oc0 + 1];
            #pragma unroll
            for (int mt = 0; mt < 2; ++mt) {
                #pragma unroll
                for (int pr2 = 0; pr2 < 2; ++pr2) {
                    float a0 = cacc[mt][n8][pr2 * 2]     + bb0;
                    float a1 = cacc[mt][n8][pr2 * 2 + 1] + bb1;
                    uint32_t pk; CVTPACK_F16(pk, a0, a1);
                    uint32_t x2, inner, arg, th, hx, g;
                    H2MUL(x2, pk, pk);
                    H2FMA(inner, C1h2, x2, C0h2);
                    H2MUL(arg, pk, inner);
                    H2TANH(th, arg);
                    H2MUL(hx, pk, Hh2);
                    H2FMA(g, hx, th, hx);
                    __half2 gh = *(__half2*)&g;
                    float2 gf = __half22float2(gh);
                    s = fmaf(gf.x, ff0, s);
                    s = fmaf(gf.y, ff1, s);
                }
            }
        }
        #pragma unroll
        for (int off = 16; off > 0; off >>= 1)
            s += __shfl_xor_sync(0xffffffffu, s, off);
        if (lane == 0) sm[SM_RED + warp] = s;

        // stage next quad into the other IN buffer (before the barrier)
        int onb = SM_IN + (buf ^ 1) * 800;
        sm[onb + st_dst0] = pf0;
        sm[onb + st_dst1] = pf1;
        __syncthreads();   // RED + IN[buf^1] ready; H1/A reads done

        if (tid < 4) {
            float v = sm[SM_RED + tid * 2] + sm[SM_RED + tid * 2 + 1];
            v = v * (1.0f / 64.0f) + sm[SM_FCB];
            int tile = tile0 + tid;
            int b = tile / (KK * TT);
            int rem = tile - b * (KK * TT);
            int k = rem / TT;
            int t = rem - k * TT;
            out[(b * TT + t) * KK + k] = v;
        }
        buf ^= 1;
        quad = nq;
    }
}

// ---------------- launch ----------------
extern "C" void kernel_launch(void* const* d_in, const int* in_sizes, int n_in,
                              void* d_out, int out_size) {
    const float* mu        = (const float*)d_in[0];
    const float* sigma0    = (const float*)d_in[1];
    const float* sigma_vel = (const float*)d_in[2];
    const float* amplitude = (const float*)d_in[3];
    const float* sh_base   = (const float*)d_in[4];
    const float* sh_vel    = (const float*)d_in[5];
    const float* p0        = (const float*)d_in[6];
    const float* p_vel     = (const float*)d_in[7];
    const float* tau_raw   = (const float*)d_in[8];
    const float* gam_raw   = (const float*)d_in[9];
    const float* limb_ra   = (const float*)d_in[10];
    const float* limb_la   = (const float*)d_in[11];
    const float* limb_ll   = (const float*)d_in[12];
    const float* chest     = (const float*)d_in[13];
    const float* conv1_w   = (const float*)d_in[14];
    const float* conv1_b   = (const float*)d_in[15];
    const float* conv2_w   = (const float*)d_in[16];
    const float* conv2_b   = (const float*)d_in[17];
    const float* fc_w      = (const float*)d_in[18];
    const float* fc_b      = (const float*)d_in[19];
    float* out = (float*)d_out;

    splat_kernel<<<dim3(TT, BB), 384>>>(mu, sigma0, sigma_vel, amplitude,
                                        sh_base, sh_vel, p0, p_vel, tau_raw, gam_raw,
                                        limb_ra, limb_la, limb_ll, chest,
                                        conv1_w, conv2_w);
    cudaFuncSetAttribute(cnn_kernel, cudaFuncAttributeMaxDynamicSharedMemorySize,
                         CNN_SMEM_BYTES);
    cnn_kernel<<<CNN_GRID, 256, CNN_SMEM_BYTES>>>(conv1_b, conv2_b, fc_w, fc_b, out);
}